// round 15
// baseline (speedup 1.0000x reference)
#include <cuda_runtime.h>
#include <cuda_fp16.h>

#define EMB 64
#define N_USER_MAX 100000
#define N_ITEM_MAX 50000
#define NMAX (N_USER_MAX + N_ITEM_MAX)
#define EMAX 4200000          // max directed edges (2*N_INTER + slack)

typedef unsigned long long u64;

// -------------------- device scratch (allocation-free rule) ----------------
__device__ __half2 g_egoh [(size_t)NMAX * 32];       // fp16 ego, ping (9.6 MB)
__device__ __half2 g_egoh2[(size_t)NMAX * 32];       // fp16 ego, pong
__device__ float   g_alle[(size_t)NMAX * EMB * 4];   // normalized concat output
__device__ int     g_deg [NMAX];                     // zeroed by gather (prev replay)
__device__ int     g_off [NMAX];                     // per-chunk-local excl scan
__device__ int     g_cur [NMAX];                     // zeroed by gather (prev replay)
__device__ int     g_bsum[128];                      // RAW chunk totals
__device__ int2    g_csr [EMAX];                     // {src, weight-bits}
__device__ int     g_idx64;

// packed fp32x2 helpers (Blackwell)
__device__ __forceinline__ u64 pk2(float lo, float hi) {
    u64 r;
    asm("mov.b64 %0, {%1,%2};" : "=l"(r) : "f"(lo), "f"(hi));
    return r;
}
__device__ __forceinline__ void fma2(u64& d, u64 a, u64 b) {
    asm("fma.rn.f32x2 %0, %1, %2, %3;" : "=l"(d) : "l"(a), "l"(b), "l"(d));
}
__device__ __forceinline__ float2 upk2(u64 v) {
    float2 r;
    asm("mov.b64 {%0,%1}, %2;" : "=f"(r.x), "=f"(r.y) : "l"(v));
    return r;
}
__device__ __forceinline__ float2 h2f(unsigned int bits) {
    __half2 h = *(__half2*)&bits;
    return __half22float2(h);
}

// ---------------------------------------------------------------------------
// Launch 0: init (alle slice0 + fp16 ego) FUSED with degree histogram.
// ---------------------------------------------------------------------------
__global__ void init_hist_kernel(const float4* __restrict__ ue,
                                 const float4* __restrict__ ie,
                                 const int* __restrict__ dst,
                                 int n_user, int n, int ne) {
    long long gid = (long long)blockIdx.x * blockDim.x + threadIdx.x;
    long long itotal = (long long)n * 16;
    if (gid < itotal) {
        int node = (int)(gid >> 4);
        int c    = (int)(gid & 15);
        float4 v = (node < n_user) ? ue[(long long)node * 16 + c]
                                   : ie[(long long)(node - n_user) * 16 + c];
        ((float4*)g_alle)[(long long)node * 64 + c] = v;   // slice 0
        g_egoh[(long long)node * 32 + 2 * c    ] = __floats2half2_rn(v.x, v.y);
        g_egoh[(long long)node * 32 + 2 * c + 1] = __floats2half2_rn(v.z, v.w);
    }
    if (gid < ne) atomicAdd(&g_deg[dst[gid]], 1);
}

// ---------------------------------------------------------------------------
// Launch 1: per-2048-chunk exclusive scan of g_deg -> g_off; raw totals->bsum
// ---------------------------------------------------------------------------
__global__ __launch_bounds__(256) void scan1_kernel(int n) {
    __shared__ int sth[256];
    int tid = threadIdx.x;
    int base = blockIdx.x * 2048 + tid * 8;
    int v[8]; int sum = 0;
#pragma unroll
    for (int j = 0; j < 8; j++) {
        v[j] = (base + j < n) ? g_deg[base + j] : 0;
        sum += v[j];
    }
    sth[tid] = sum;
    __syncthreads();
    for (int o = 1; o < 256; o <<= 1) {
        int t = (tid >= o) ? sth[tid - o] : 0;
        __syncthreads();
        sth[tid] += t;
        __syncthreads();
    }
    int run = (tid > 0) ? sth[tid - 1] : 0;
#pragma unroll
    for (int j = 0; j < 8; j++) {
        if (base + j < n) g_off[base + j] = run;
        run += v[j];
    }
    if (tid == 255) g_bsum[blockIdx.x] = sth[255];
}

// Inclusive scan of g_bsum into sb[128]; all 256 threads participate.
__device__ __forceinline__ void block_scan_bsum(int* sb, int nchunks) {
    int tid = threadIdx.x;
    if (tid < 128) sb[tid] = (tid < nchunks) ? g_bsum[tid] : 0;
    __syncthreads();
    for (int o = 1; o < 128; o <<= 1) {
        int t = (tid >= o && tid < 128) ? sb[tid - o] : 0;
        __syncthreads();
        if (tid < 128) sb[tid] += t;
        __syncthreads();
    }
}

// ---------------------------------------------------------------------------
// Launch 2: fill CSR (inline chunk-base scan)
// ---------------------------------------------------------------------------
__global__ __launch_bounds__(256) void fill_kernel(const int* __restrict__ src,
                                                   const int* __restrict__ dst,
                                                   const float* __restrict__ w,
                                                   int ne, int nchunks) {
    __shared__ int sb[128];
    block_scan_bsum(sb, nchunks);
    int e = blockIdx.x * blockDim.x + threadIdx.x;
    if (e >= ne) return;
    int d = dst[e];
    int cb = (d >> 11) ? sb[(d >> 11) - 1] : 0;
    int pos = g_off[d] + cb + atomicAdd(&g_cur[d], 1);
    if (pos < EMAX)
        g_csr[pos] = make_int2(src[e], __float_as_int(w[e]));
}

// ---------------------------------------------------------------------------
// Launches 3-5: fused layer. Warp handles 8 nodes.
//   Phase 1: pull-aggregate side from fp16 ego rows (smem-staged edges),
//            stage packed {side_i, (ego*side)_i} u64 per (node, i).
//   Phase 2: fused dual GEMV, i in PAIRS: one LDS.128 broadcast per node
//            covers 2 iterations; W tile read once per 8 nodes.
//            1 L1 wavefront per iter per node (was 2).
//   Phase 3: e = lo + hi, leaky_relu, norm, store fp16 ego + fp32 alle.
// ---------------------------------------------------------------------------
__global__ __launch_bounds__(256, 3) void layer_kernel(
        const float* __restrict__ Wg, const float* __restrict__ bg,
        const float* __restrict__ Wb, const float* __restrict__ bb,
        const __half2* __restrict__ egoh_in, __half2* __restrict__ egoh_out,
        int n, int koff, int nchunks) {
    __shared__ float4 sW[EMB][32];      // {wg[i][2l], wb[i][2l], wg[i][2l+1], wb[i][2l+1]}
    __shared__ float4 sbias[32];        // {bg2l, bb2l, bg2l+1, bb2l+1}
    __shared__ u64    sxx[8][8][EMB];   // {side_i, bi_i} per (warp, node, i)
    __shared__ int2   sed[8][32];       // staged CSR edges per warp
    __shared__ int    sb[128];          // chunk-base inclusive scan

    int tid = threadIdx.x;
    for (int e = tid; e < EMB * 32; e += 256) {
        int i = e >> 5, l = e & 31;
        sW[i][l] = make_float4(Wg[i * EMB + 2 * l], Wb[i * EMB + 2 * l],
                               Wg[i * EMB + 2 * l + 1], Wb[i * EMB + 2 * l + 1]);
    }
    if (tid < 32)
        sbias[tid] = make_float4(bg[2 * tid], bb[2 * tid],
                                 bg[2 * tid + 1], bb[2 * tid + 1]);
    block_scan_bsum(sb, nchunks);       // includes needed __syncthreads

    int warp = tid >> 5;
    int lane = tid & 31;
    const unsigned FULL = 0xFFFFFFFFu;
    const unsigned int* egou = (const unsigned int*)egoh_in;

    int qbase = (blockIdx.x * 8 + warp) * 8;
    if (qbase >= n) return;

    // ---- Phase 1: aggregate 8 nodes, stage packed {side, bi} ----
#pragma unroll
    for (int nd = 0; nd < 8; nd++) {
        int node = qbase + nd;
        float2 side = make_float2(0.f, 0.f);
        float2 eg   = make_float2(0.f, 0.f);
        if (node < n) {
            int cb      = (node >> 11) ? sb[(node >> 11) - 1] : 0;
            int beg     = g_off[node] + cb;
            int cnt_all = g_deg[node];
            float2 a0 = {0.f,0.f}, a1 = {0.f,0.f}, a2 = {0.f,0.f}, a3 = {0.f,0.f};
            for (int base = 0; base < cnt_all; base += 32) {
                if (base + lane < cnt_all)
                    sed[warp][lane] = g_csr[beg + base + lane];
                __syncwarp();
                int cnt = min(32, cnt_all - base);
                int k = 0;
                for (; k + 8 <= cnt; k += 8) {
                    unsigned int hv[8]; float w[8];
#pragma unroll
                    for (int j = 0; j < 8; j++) {
                        int2 e = sed[warp][k + j];          // LDS.64 broadcast
                        w[j]  = __int_as_float(e.y);
                        hv[j] = __ldcg(egou + e.x * 32 + lane);
                    }
#pragma unroll
                    for (int j = 0; j < 8; j++) {
                        float2 v = h2f(hv[j]);
                        float2* a = (j & 2) ? ((j & 1) ? &a3 : &a2)
                                            : ((j & 1) ? &a1 : &a0);
                        a->x = fmaf(w[j], v.x, a->x);
                        a->y = fmaf(w[j], v.y, a->y);
                    }
                }
                for (; k + 4 <= cnt; k += 4) {
                    unsigned int hv[4]; float w[4];
#pragma unroll
                    for (int j = 0; j < 4; j++) {
                        int2 e = sed[warp][k + j];
                        w[j]  = __int_as_float(e.y);
                        hv[j] = __ldcg(egou + e.x * 32 + lane);
                    }
                    float2 v0 = h2f(hv[0]), v1 = h2f(hv[1]);
                    float2 v2 = h2f(hv[2]), v3 = h2f(hv[3]);
                    a0.x = fmaf(w[0], v0.x, a0.x); a0.y = fmaf(w[0], v0.y, a0.y);
                    a1.x = fmaf(w[1], v1.x, a1.x); a1.y = fmaf(w[1], v1.y, a1.y);
                    a2.x = fmaf(w[2], v2.x, a2.x); a2.y = fmaf(w[2], v2.y, a2.y);
                    a3.x = fmaf(w[3], v3.x, a3.x); a3.y = fmaf(w[3], v3.y, a3.y);
                }
                for (; k < cnt; k++) {
                    int2 e = sed[warp][k];
                    float ww = __int_as_float(e.y);
                    float2 v = h2f(__ldcg(egou + e.x * 32 + lane));
                    a0.x = fmaf(ww, v.x, a0.x); a0.y = fmaf(ww, v.y, a0.y);
                }
                __syncwarp();
            }
            side.x = (a0.x + a1.x) + (a2.x + a3.x);
            side.y = (a0.y + a1.y) + (a2.y + a3.y);
            eg = h2f(egou[node * 32 + lane]);
        }
        // one conflict-free STS.128: rows 2l, 2l+1 for this node
        u64 lo = pk2(side.x, eg.x * side.x);
        u64 hi = pk2(side.y, eg.y * side.y);
        *(ulonglong2*)&sxx[warp][nd][2 * lane] = make_ulonglong2(lo, hi);
    }
    __syncwarp();

    // ---- Phase 2: fused dual GEMV, paired i (lo chain = Wg, hi chain = Wb) ----
    float4 bv = sbias[lane];
    u64 b0 = pk2(bv.x, bv.y);           // {bg[2l],  bb[2l]}
    u64 b1 = pk2(bv.z, bv.w);           // {bg[2l+1],bb[2l+1]}
    u64 acc[8][2];
#pragma unroll
    for (int nd = 0; nd < 8; nd++) { acc[nd][0] = b0; acc[nd][1] = b1; }

#pragma unroll 4
    for (int i = 0; i < EMB; i += 2) {
        ulonglong2 wv0 = *(const ulonglong2*)&sW[i    ][lane];  // LDS.128
        ulonglong2 wv1 = *(const ulonglong2*)&sW[i + 1][lane];  // LDS.128
#pragma unroll
        for (int nd = 0; nd < 8; nd++) {
            ulonglong2 x = *(const ulonglong2*)&sxx[warp][nd][i];  // broadcast
            fma2(acc[nd][0], x.x, wv0.x); fma2(acc[nd][1], x.x, wv0.y);
            fma2(acc[nd][0], x.y, wv1.x); fma2(acc[nd][1], x.y, wv1.y);
        }
    }

    // ---- Phase 3: e = lo + hi, activation + norm + store ----
#pragma unroll
    for (int nd = 0; nd < 8; nd++) {
        int node = qbase + nd;
        float2 c0 = upk2(acc[nd][0]);   // {accg[2l],   accb[2l]}
        float2 c1 = upk2(acc[nd][1]);   // {accg[2l+1], accb[2l+1]}
        float2 e2;
        e2.x = c0.x + c0.y;
        e2.y = c1.x + c1.y;
        e2.x = (e2.x >= 0.f) ? e2.x : 0.2f * e2.x;
        e2.y = (e2.y >= 0.f) ? e2.y : 0.2f * e2.y;
        float ssq = e2.x * e2.x + e2.y * e2.y;
#pragma unroll
        for (int o = 16; o > 0; o >>= 1) ssq += __shfl_xor_sync(FULL, ssq, o);
        float inv = 1.f / fmaxf(sqrtf(ssq), 1e-12f);
        if (node < n) {
            egoh_out[node * 32 + lane] = __floats2half2_rn(e2.x, e2.y);
            *(float2*)&g_alle[(long long)node * 256 + koff + 2 * lane] =
                make_float2(e2.x * inv, e2.y * inv);
        }
    }
}

// ---------------------------------------------------------------------------
// int64 vs int32 index detection (odd 32-bit words all zero => int64 LE)
// ---------------------------------------------------------------------------
__global__ void detect_kernel(const int* __restrict__ users, int nb) {
    __shared__ int s;
    if (threadIdx.x == 0) s = 0;
    __syncthreads();
    int acc = 0;
    for (int i = threadIdx.x; i < nb / 2; i += blockDim.x)
        acc |= users[2 * i + 1];
    atomicOr(&s, acc);
    __syncthreads();
    if (threadIdx.x == 0) g_idx64 = (s == 0) ? 1 : 0;
}

// ---------------------------------------------------------------------------
// Gather outputs + re-zero g_deg/g_cur for the next (identical) replay.
// ---------------------------------------------------------------------------
__global__ void gather_kernel(const void* __restrict__ users,
                              const void* __restrict__ pos,
                              const void* __restrict__ neg,
                              float* __restrict__ out,
                              int n_user, int n, int nb) {
    int flag = g_idx64;
    long long gid = (long long)blockIdx.x * blockDim.x + threadIdx.x;
    if (gid < n) { g_deg[gid] = 0; g_cur[gid] = 0; }
    long long total = 3LL * nb * 64;
    if (gid >= total) return;
    int c = (int)(gid & 63);
    long long r = gid >> 6;
    int which = (int)(r / nb);
    int b     = (int)(r % nb);
    const void* p = (which == 0) ? users : (which == 1) ? pos : neg;
    long long idx = flag ? ((const long long*)p)[b]
                         : (long long)((const int*)p)[b];
    long long row = (which == 0) ? idx : ((long long)n_user + idx);
    ((float4*)out)[gid] = ((const float4*)g_alle)[row * 64 + c];
}

// ---------------------------------------------------------------------------
extern "C" void kernel_launch(void* const* d_in, const int* in_sizes, int n_in,
                              void* d_out, int out_size) {
    const float* user_emb = (const float*)d_in[0];
    const float* item_emb = (const float*)d_in[1];
    const float* W_gc     = (const float*)d_in[2];
    const float* b_gc     = (const float*)d_in[3];
    const float* W_bi     = (const float*)d_in[4];
    const float* b_bi     = (const float*)d_in[5];
    const float* edge_w   = (const float*)d_in[6];
    const int*   edge_src = (const int*)d_in[7];
    const int*   edge_dst = (const int*)d_in[8];
    const void*  users    = d_in[9];
    const void*  pos      = d_in[10];
    const void*  neg      = d_in[11];

    int n_user  = in_sizes[0] / EMB;
    int n_item  = in_sizes[1] / EMB;
    int n       = n_user + n_item;
    int n_edges = in_sizes[6];
    int layers  = in_sizes[2] / (EMB * EMB);
    int nb      = in_sizes[9];
    int nchunks = (n + 2047) / 2048;

    // (0) init + degree histogram
    {
        long long total = (long long)n * 16;
        if ((long long)n_edges > total) total = n_edges;
        init_hist_kernel<<<(int)((total + 255) / 256), 256>>>(
            (const float4*)user_emb, (const float4*)item_emb, edge_dst,
            n_user, n, n_edges);
    }

    // (1) chunk-local scans + raw chunk totals
    scan1_kernel<<<nchunks, 256>>>(n);

    // (2) CSR fill
    fill_kernel<<<(n_edges + 255) / 256, 256>>>(edge_src, edge_dst, edge_w,
                                                n_edges, nchunks);

    // (3-5) fused layers, fp16 ego ping-pong — layer0 at ncu slot 3
    __half2 *eA = nullptr, *eB = nullptr;
    cudaGetSymbolAddress((void**)&eA, g_egoh);
    cudaGetSymbolAddress((void**)&eB, g_egoh2);
    __half2* cur = eA; __half2* nxt = eB;
    int lblocks = (n + 63) / 64;             // 1 warp per 8 nodes
    for (int k = 0; k < layers; k++) {
        layer_kernel<<<lblocks, 256>>>(W_gc + (long long)k * EMB * EMB,
                                       b_gc + (long long)k * EMB,
                                       W_bi + (long long)k * EMB * EMB,
                                       b_bi + (long long)k * EMB,
                                       cur, nxt, n, EMB * (k + 1), nchunks);
        __half2* t = cur; cur = nxt; nxt = t;
    }

    // (6) dtype detect, (7) gather + state re-zero
    detect_kernel<<<1, 256>>>((const int*)users, nb);
    {
        long long total = 3LL * nb * 64;
        gather_kernel<<<(int)((total + 255) / 256), 256>>>(
            users, pos, neg, (float*)d_out, n_user, n, nb);
    }
}

// round 16
// speedup vs baseline: 1.0943x; 1.0943x over previous
#include <cuda_runtime.h>
#include <cuda_fp16.h>

#define EMB 64
#define N_USER_MAX 100000
#define N_ITEM_MAX 50000
#define NMAX (N_USER_MAX + N_ITEM_MAX)
#define EMAX 4200000          // max directed edges (2*N_INTER + slack)

typedef unsigned long long u64;

// -------------------- device scratch (allocation-free rule) ----------------
__device__ __half2 g_egoh [(size_t)NMAX * 32];       // fp16 ego, ping (9.6 MB)
__device__ __half2 g_egoh2[(size_t)NMAX * 32];       // fp16 ego, pong
__device__ float   g_alle[(size_t)NMAX * EMB * 4];   // normalized concat output
__device__ int     g_deg [NMAX];                     // zeroed by gather (prev replay)
__device__ int     g_off [NMAX];                     // per-chunk-local excl scan
__device__ int     g_cur [NMAX];                     // zeroed by gather (prev replay)
__device__ int     g_bsum[128];                      // RAW chunk totals
__device__ int2    g_csr [EMAX];                     // {src, weight-bits}
__device__ int     g_idx64;

// packed fp32x2 helpers (Blackwell)
__device__ __forceinline__ u64 pk2(float lo, float hi) {
    u64 r;
    asm("mov.b64 %0, {%1,%2};" : "=l"(r) : "f"(lo), "f"(hi));
    return r;
}
__device__ __forceinline__ void fma2(u64& d, u64 a, u64 b) {
    asm("fma.rn.f32x2 %0, %1, %2, %3;" : "=l"(d) : "l"(a), "l"(b), "l"(d));
}
__device__ __forceinline__ float2 upk2(u64 v) {
    float2 r;
    asm("mov.b64 {%0,%1}, %2;" : "=f"(r.x), "=f"(r.y) : "l"(v));
    return r;
}
__device__ __forceinline__ float2 h2f(unsigned int bits) {
    __half2 h = *(__half2*)&bits;
    return __half22float2(h);
}

// ---------------------------------------------------------------------------
// Launch 0: init (alle slice0 + fp16 ego) FUSED with degree histogram.
// ---------------------------------------------------------------------------
__global__ void init_hist_kernel(const float4* __restrict__ ue,
                                 const float4* __restrict__ ie,
                                 const int* __restrict__ dst,
                                 int n_user, int n, int ne) {
    long long gid = (long long)blockIdx.x * blockDim.x + threadIdx.x;
    long long itotal = (long long)n * 16;
    if (gid < itotal) {
        int node = (int)(gid >> 4);
        int c    = (int)(gid & 15);
        float4 v = (node < n_user) ? ue[(long long)node * 16 + c]
                                   : ie[(long long)(node - n_user) * 16 + c];
        ((float4*)g_alle)[(long long)node * 64 + c] = v;   // slice 0
        g_egoh[(long long)node * 32 + 2 * c    ] = __floats2half2_rn(v.x, v.y);
        g_egoh[(long long)node * 32 + 2 * c + 1] = __floats2half2_rn(v.z, v.w);
    }
    if (gid < ne) atomicAdd(&g_deg[dst[gid]], 1);
}

// ---------------------------------------------------------------------------
// Launch 1: per-2048-chunk exclusive scan of g_deg -> g_off; raw totals->bsum
// ---------------------------------------------------------------------------
__global__ __launch_bounds__(256) void scan1_kernel(int n) {
    __shared__ int sth[256];
    int tid = threadIdx.x;
    int base = blockIdx.x * 2048 + tid * 8;
    int v[8]; int sum = 0;
#pragma unroll
    for (int j = 0; j < 8; j++) {
        v[j] = (base + j < n) ? g_deg[base + j] : 0;
        sum += v[j];
    }
    sth[tid] = sum;
    __syncthreads();
    for (int o = 1; o < 256; o <<= 1) {
        int t = (tid >= o) ? sth[tid - o] : 0;
        __syncthreads();
        sth[tid] += t;
        __syncthreads();
    }
    int run = (tid > 0) ? sth[tid - 1] : 0;
#pragma unroll
    for (int j = 0; j < 8; j++) {
        if (base + j < n) g_off[base + j] = run;
        run += v[j];
    }
    if (tid == 255) g_bsum[blockIdx.x] = sth[255];
}

// Inclusive scan of g_bsum into sb[128]; all 256 threads participate.
__device__ __forceinline__ void block_scan_bsum(int* sb, int nchunks) {
    int tid = threadIdx.x;
    if (tid < 128) sb[tid] = (tid < nchunks) ? g_bsum[tid] : 0;
    __syncthreads();
    for (int o = 1; o < 128; o <<= 1) {
        int t = (tid >= o && tid < 128) ? sb[tid - o] : 0;
        __syncthreads();
        if (tid < 128) sb[tid] += t;
        __syncthreads();
    }
}

// ---------------------------------------------------------------------------
// Launch 2: fill CSR (inline chunk-base scan)
// ---------------------------------------------------------------------------
__global__ __launch_bounds__(256) void fill_kernel(const int* __restrict__ src,
                                                   const int* __restrict__ dst,
                                                   const float* __restrict__ w,
                                                   int ne, int nchunks) {
    __shared__ int sb[128];
    block_scan_bsum(sb, nchunks);
    int e = blockIdx.x * blockDim.x + threadIdx.x;
    if (e >= ne) return;
    int d = dst[e];
    int cb = (d >> 11) ? sb[(d >> 11) - 1] : 0;
    int pos = g_off[d] + cb + atomicAdd(&g_cur[d], 1);
    if (pos < EMAX)
        g_csr[pos] = make_int2(src[e], __float_as_int(w[e]));
}

// ---------------------------------------------------------------------------
// Launches 3-5: fused layer (R14 config: 4 nodes/warp, occ 4 blocks/SM).
//   Phase 1: pull-aggregate side from fp16 ego rows (smem-staged edges),
//            stage packed {side_i, (ego*side)_i} u64 per (node, i).
//   Phase 2: fused dual GEMV with PAIRED-i reads: one LDS.128 broadcast per
//            node covers 2 iterations; 22 instr / 12 wf per 2 iters (was 26/16).
//   Phase 3: e = lo + hi, leaky_relu, norm, store fp16 ego + fp32 alle.
// ---------------------------------------------------------------------------
__global__ __launch_bounds__(256, 4) void layer_kernel(
        const float* __restrict__ Wg, const float* __restrict__ bg,
        const float* __restrict__ Wb, const float* __restrict__ bb,
        const __half2* __restrict__ egoh_in, __half2* __restrict__ egoh_out,
        int n, int koff, int nchunks) {
    __shared__ float4 sW[EMB][32];      // {wg[i][2l], wb[i][2l], wg[i][2l+1], wb[i][2l+1]}
    __shared__ float4 sbias[32];        // {bg2l, bb2l, bg2l+1, bb2l+1}
    __shared__ u64    sxx[8][4][EMB];   // {side_i, bi_i} per (warp, node, i)
    __shared__ int2   sed[8][32];       // staged CSR edges per warp
    __shared__ int    sb[128];          // chunk-base inclusive scan

    int tid = threadIdx.x;
    for (int e = tid; e < EMB * 32; e += 256) {
        int i = e >> 5, l = e & 31;
        sW[i][l] = make_float4(Wg[i * EMB + 2 * l], Wb[i * EMB + 2 * l],
                               Wg[i * EMB + 2 * l + 1], Wb[i * EMB + 2 * l + 1]);
    }
    if (tid < 32)
        sbias[tid] = make_float4(bg[2 * tid], bb[2 * tid],
                                 bg[2 * tid + 1], bb[2 * tid + 1]);
    block_scan_bsum(sb, nchunks);       // includes needed __syncthreads

    int warp = tid >> 5;
    int lane = tid & 31;
    const unsigned FULL = 0xFFFFFFFFu;
    const unsigned int* egou = (const unsigned int*)egoh_in;

    int qbase = (blockIdx.x * 8 + warp) * 4;
    if (qbase >= n) return;

    // ---- Phase 1: aggregate 4 nodes, stage packed {side, bi} ----
#pragma unroll
    for (int nd = 0; nd < 4; nd++) {
        int node = qbase + nd;
        float2 side = make_float2(0.f, 0.f);
        float2 eg   = make_float2(0.f, 0.f);
        if (node < n) {
            int cb      = (node >> 11) ? sb[(node >> 11) - 1] : 0;
            int beg     = g_off[node] + cb;
            int cnt_all = g_deg[node];
            float2 a0 = {0.f,0.f}, a1 = {0.f,0.f}, a2 = {0.f,0.f}, a3 = {0.f,0.f};
            for (int base = 0; base < cnt_all; base += 32) {
                if (base + lane < cnt_all)
                    sed[warp][lane] = g_csr[beg + base + lane];
                __syncwarp();
                int cnt = min(32, cnt_all - base);
                int k = 0;
                for (; k + 8 <= cnt; k += 8) {
                    unsigned int hv[8]; float w[8];
#pragma unroll
                    for (int j = 0; j < 8; j++) {
                        int2 e = sed[warp][k + j];          // LDS.64 broadcast
                        w[j]  = __int_as_float(e.y);
                        hv[j] = __ldcg(egou + e.x * 32 + lane);
                    }
#pragma unroll
                    for (int j = 0; j < 8; j++) {
                        float2 v = h2f(hv[j]);
                        float2* a = (j & 2) ? ((j & 1) ? &a3 : &a2)
                                            : ((j & 1) ? &a1 : &a0);
                        a->x = fmaf(w[j], v.x, a->x);
                        a->y = fmaf(w[j], v.y, a->y);
                    }
                }
                for (; k + 4 <= cnt; k += 4) {
                    unsigned int hv[4]; float w[4];
#pragma unroll
                    for (int j = 0; j < 4; j++) {
                        int2 e = sed[warp][k + j];
                        w[j]  = __int_as_float(e.y);
                        hv[j] = __ldcg(egou + e.x * 32 + lane);
                    }
                    float2 v0 = h2f(hv[0]), v1 = h2f(hv[1]);
                    float2 v2 = h2f(hv[2]), v3 = h2f(hv[3]);
                    a0.x = fmaf(w[0], v0.x, a0.x); a0.y = fmaf(w[0], v0.y, a0.y);
                    a1.x = fmaf(w[1], v1.x, a1.x); a1.y = fmaf(w[1], v1.y, a1.y);
                    a2.x = fmaf(w[2], v2.x, a2.x); a2.y = fmaf(w[2], v2.y, a2.y);
                    a3.x = fmaf(w[3], v3.x, a3.x); a3.y = fmaf(w[3], v3.y, a3.y);
                }
                for (; k < cnt; k++) {
                    int2 e = sed[warp][k];
                    float ww = __int_as_float(e.y);
                    float2 v = h2f(__ldcg(egou + e.x * 32 + lane));
                    a0.x = fmaf(ww, v.x, a0.x); a0.y = fmaf(ww, v.y, a0.y);
                }
                __syncwarp();
            }
            side.x = (a0.x + a1.x) + (a2.x + a3.x);
            side.y = (a0.y + a1.y) + (a2.y + a3.y);
            eg = h2f(egou[node * 32 + lane]);
        }
        // one conflict-free STS.128: rows 2l, 2l+1 for this node
        u64 lo = pk2(side.x, eg.x * side.x);
        u64 hi = pk2(side.y, eg.y * side.y);
        *(ulonglong2*)&sxx[warp][nd][2 * lane] = make_ulonglong2(lo, hi);
    }
    __syncwarp();

    // ---- Phase 2: fused dual GEMV, paired-i (lo chain = Wg, hi chain = Wb) ----
    float4 bv = sbias[lane];
    u64 b0 = pk2(bv.x, bv.y);           // {bg[2l],  bb[2l]}
    u64 b1 = pk2(bv.z, bv.w);           // {bg[2l+1],bb[2l+1]}
    u64 acc[4][2];
#pragma unroll
    for (int nd = 0; nd < 4; nd++) { acc[nd][0] = b0; acc[nd][1] = b1; }

#pragma unroll 4
    for (int i = 0; i < EMB; i += 2) {
        ulonglong2 wv0 = *(const ulonglong2*)&sW[i    ][lane];   // LDS.128
        ulonglong2 wv1 = *(const ulonglong2*)&sW[i + 1][lane];   // LDS.128
        ulonglong2 x0 = *(const ulonglong2*)&sxx[warp][0][i];    // {x_i, x_i+1}
        ulonglong2 x1 = *(const ulonglong2*)&sxx[warp][1][i];
        ulonglong2 x2 = *(const ulonglong2*)&sxx[warp][2][i];
        ulonglong2 x3 = *(const ulonglong2*)&sxx[warp][3][i];
        fma2(acc[0][0], x0.x, wv0.x); fma2(acc[0][1], x0.x, wv0.y);
        fma2(acc[0][0], x0.y, wv1.x); fma2(acc[0][1], x0.y, wv1.y);
        fma2(acc[1][0], x1.x, wv0.x); fma2(acc[1][1], x1.x, wv0.y);
        fma2(acc[1][0], x1.y, wv1.x); fma2(acc[1][1], x1.y, wv1.y);
        fma2(acc[2][0], x2.x, wv0.x); fma2(acc[2][1], x2.x, wv0.y);
        fma2(acc[2][0], x2.y, wv1.x); fma2(acc[2][1], x2.y, wv1.y);
        fma2(acc[3][0], x3.x, wv0.x); fma2(acc[3][1], x3.x, wv0.y);
        fma2(acc[3][0], x3.y, wv1.x); fma2(acc[3][1], x3.y, wv1.y);
    }

    // ---- Phase 3: e = lo + hi, activation + norm + store ----
#pragma unroll
    for (int nd = 0; nd < 4; nd++) {
        int node = qbase + nd;
        float2 c0 = upk2(acc[nd][0]);   // {accg[2l],   accb[2l]}
        float2 c1 = upk2(acc[nd][1]);   // {accg[2l+1], accb[2l+1]}
        float2 e2;
        e2.x = c0.x + c0.y;
        e2.y = c1.x + c1.y;
        e2.x = (e2.x >= 0.f) ? e2.x : 0.2f * e2.x;
        e2.y = (e2.y >= 0.f) ? e2.y : 0.2f * e2.y;
        float ssq = e2.x * e2.x + e2.y * e2.y;
#pragma unroll
        for (int o = 16; o > 0; o >>= 1) ssq += __shfl_xor_sync(FULL, ssq, o);
        float inv = 1.f / fmaxf(sqrtf(ssq), 1e-12f);
        if (node < n) {
            egoh_out[node * 32 + lane] = __floats2half2_rn(e2.x, e2.y);
            *(float2*)&g_alle[(long long)node * 256 + koff + 2 * lane] =
                make_float2(e2.x * inv, e2.y * inv);
        }
    }
}

// ---------------------------------------------------------------------------
// int64 vs int32 index detection (odd 32-bit words all zero => int64 LE)
// ---------------------------------------------------------------------------
__global__ void detect_kernel(const int* __restrict__ users, int nb) {
    __shared__ int s;
    if (threadIdx.x == 0) s = 0;
    __syncthreads();
    int acc = 0;
    for (int i = threadIdx.x; i < nb / 2; i += blockDim.x)
        acc |= users[2 * i + 1];
    atomicOr(&s, acc);
    __syncthreads();
    if (threadIdx.x == 0) g_idx64 = (s == 0) ? 1 : 0;
}

// ---------------------------------------------------------------------------
// Gather outputs + re-zero g_deg/g_cur for the next (identical) replay.
// ---------------------------------------------------------------------------
__global__ void gather_kernel(const void* __restrict__ users,
                              const void* __restrict__ pos,
                              const void* __restrict__ neg,
                              float* __restrict__ out,
                              int n_user, int n, int nb) {
    int flag = g_idx64;
    long long gid = (long long)blockIdx.x * blockDim.x + threadIdx.x;
    if (gid < n) { g_deg[gid] = 0; g_cur[gid] = 0; }
    long long total = 3LL * nb * 64;
    if (gid >= total) return;
    int c = (int)(gid & 63);
    long long r = gid >> 6;
    int which = (int)(r / nb);
    int b     = (int)(r % nb);
    const void* p = (which == 0) ? users : (which == 1) ? pos : neg;
    long long idx = flag ? ((const long long*)p)[b]
                         : (long long)((const int*)p)[b];
    long long row = (which == 0) ? idx : ((long long)n_user + idx);
    ((float4*)out)[gid] = ((const float4*)g_alle)[row * 64 + c];
}

// ---------------------------------------------------------------------------
extern "C" void kernel_launch(void* const* d_in, const int* in_sizes, int n_in,
                              void* d_out, int out_size) {
    const float* user_emb = (const float*)d_in[0];
    const float* item_emb = (const float*)d_in[1];
    const float* W_gc     = (const float*)d_in[2];
    const float* b_gc     = (const float*)d_in[3];
    const float* W_bi     = (const float*)d_in[4];
    const float* b_bi     = (const float*)d_in[5];
    const float* edge_w   = (const float*)d_in[6];
    const int*   edge_src = (const int*)d_in[7];
    const int*   edge_dst = (const int*)d_in[8];
    const void*  users    = d_in[9];
    const void*  pos      = d_in[10];
    const void*  neg      = d_in[11];

    int n_user  = in_sizes[0] / EMB;
    int n_item  = in_sizes[1] / EMB;
    int n       = n_user + n_item;
    int n_edges = in_sizes[6];
    int layers  = in_sizes[2] / (EMB * EMB);
    int nb      = in_sizes[9];
    int nchunks = (n + 2047) / 2048;

    // (0) init + degree histogram
    {
        long long total = (long long)n * 16;
        if ((long long)n_edges > total) total = n_edges;
        init_hist_kernel<<<(int)((total + 255) / 256), 256>>>(
            (const float4*)user_emb, (const float4*)item_emb, edge_dst,
            n_user, n, n_edges);
    }

    // (1) chunk-local scans + raw chunk totals
    scan1_kernel<<<nchunks, 256>>>(n);

    // (2) CSR fill
    fill_kernel<<<(n_edges + 255) / 256, 256>>>(edge_src, edge_dst, edge_w,
                                                n_edges, nchunks);

    // (3-5) fused layers, fp16 ego ping-pong — layer0 at ncu slot 3
    __half2 *eA = nullptr, *eB = nullptr;
    cudaGetSymbolAddress((void**)&eA, g_egoh);
    cudaGetSymbolAddress((void**)&eB, g_egoh2);
    __half2* cur = eA; __half2* nxt = eB;
    int lblocks = (n + 31) / 32;             // 1 warp per 4 nodes
    for (int k = 0; k < layers; k++) {
        layer_kernel<<<lblocks, 256>>>(W_gc + (long long)k * EMB * EMB,
                                       b_gc + (long long)k * EMB,
                                       W_bi + (long long)k * EMB * EMB,
                                       b_bi + (long long)k * EMB,
                                       cur, nxt, n, EMB * (k + 1), nchunks);
        __half2* t = cur; cur = nxt; nxt = t;
    }

    // (6) dtype detect, (7) gather + state re-zero
    detect_kernel<<<1, 256>>>((const int*)users, nb);
    {
        long long total = 3LL * nb * 64;
        gather_kernel<<<(int)((total + 255) / 256), 256>>>(
            users, pos, neg, (float*)d_out, n_user, n, nb);
    }
}